// round 10
// baseline (speedup 1.0000x reference)
#include <cuda_runtime.h>
#include <math.h>
#include <stdint.h>

#define HIN     14
#define WIN     14
#define HO      12
#define WO      12
#define BATCH   4
#define FIN     32
#define DIN     8
#define FF      32
#define CCAP    288
#define DOUT    16
#define NPOS    (BATCH*HO*WO)   // 576

// both passes: 4 warps/CTA, 4 pos/warp -> 16 pos/CTA; 8 c-chunks of 36
// grid 36 x 8 = 288 CTAs, 2 CTAs/SM -> one wave on 148 SMs
#define TPB     128
#define POSB    16
#define NPB     (NPOS/POSB)     // 36
#define NCH     8
#define CPC     (CCAP/NCH)      // 36  (18 duets)

#define SMEM_W_BYTES  (4 * 2048 * 8)                 // 4 stages x 16KB = 64KB
#define SMEM_O1_BYTES (8 * POSB * 32 * 8)            // [p][pos][f] u64 = 32KB
#define SMEM1_BYTES   SMEM_W_BYTES                   // pass1: 64KB
#define SMEM2_BYTES   (SMEM_W_BYTES + SMEM_O1_BYTES) // pass2: 96KB

typedef unsigned long long u64;

// ---------------- scratch (static device globals) ---------------------------
// Wq[c][i(8)][ph(4)][f(32)] : ulonglong2 = pairs { (W[2ph,i],W[2ph+8,i]), (W[2ph+1,i],W[2ph+9,i]) }
__device__ ulonglong2 g_Wq[(size_t)CCAP*8*4*32];              // 4.7 MB
__device__ float2 g_S1p[(size_t)NCH*NPOS*FF*8];               // pass1 partials
__device__ float2 g_out1p[(size_t)NPOS*FF*8];                 // squash(iter1) fp32 pairs
__device__ float2 g_centp[(size_t)NCH*NPOS*FF*8];             // pass2 partial centroids

__device__ __constant__ int c_koff[9] = {0, 256, 512, 3584, 3840, 4096, 7168, 7424, 7680};

// ---------------- f32x2 helpers ---------------------------------------------
__device__ __forceinline__ u64 pk(float lo, float hi) {
    u64 r; asm("mov.b64 %0,{%1,%2};" : "=l"(r) : "f"(lo), "f"(hi)); return r;
}
__device__ __forceinline__ void upk(u64 v, float& a, float& b) {
    asm("mov.b64 {%0,%1},%2;" : "=f"(a), "=f"(b) : "l"(v));
}
__device__ __forceinline__ u64 fma2(u64 a, u64 b, u64 c) {
    u64 d; asm("fma.rn.f32x2 %0,%1,%2,%3;" : "=l"(d) : "l"(a), "l"(b), "l"(c)); return d;
}

// ---------------- cp.async helpers -------------------------------------------
__device__ __forceinline__ void cp16(uint32_t saddr, const void* gaddr) {
    asm volatile("cp.async.cg.shared.global [%0], [%1], 16;" :: "r"(saddr), "l"(gaddr));
}
// copy one 16KB W tile (1024 x 16B) into a smem stage; commits one group
__device__ __forceinline__ void stage_copy(u64* sdst, const ulonglong2* gsrc, int tid) {
    uint32_t s = (uint32_t)__cvta_generic_to_shared(sdst);
    const char* g = (const char*)gsrc;
    #pragma unroll
    for (int k = 0; k < 8; ++k) {          // 8 * 128 = 1024 chunks
        int idx = tid + k * TPB;
        cp16(s + idx * 16, g + (size_t)idx * 16);
    }
    asm volatile("cp.async.commit_group;");
}
template<int N>
__device__ __forceinline__ void wait_cp() {
    asm volatile("cp.async.wait_group %0;" :: "n"(N));
}

// ---------------- W transform: W[f][c][o][i] -> Wq quad layout ---------------
__global__ void k_transpose(const float* __restrict__ W) {
    int tid = blockIdx.x * blockDim.x + threadIdx.x;
    if (tid >= CCAP * 8 * 4 * 32) return;
    int f  = tid & 31;
    int r  = tid >> 5;
    int ph = r & 3;
    int i  = (r >> 2) & 7;
    int c  = r >> 5;
    int p0 = 2 * ph;
    const float* base = W + ((size_t)f * CCAP + c) * DOUT * DIN;
    float w0  = base[(p0)     * DIN + i];
    float w0h = base[(p0 + 8) * DIN + i];
    float w1  = base[(p0 + 1) * DIN + i];
    float w1h = base[(p0 + 9) * DIN + i];
    ulonglong2 v;
    v.x = pk(w0, w0h);
    v.y = pk(w1, w1h);
    g_Wq[(((size_t)c * 8 + i) * 4 + ph) * 32 + f] = v;
}

__device__ __forceinline__ const float* pos_base(const float* x, int pos) {
    int b = pos / (HO * WO);
    int r = pos % (HO * WO);
    int h = r / WO;
    int w = r % WO;
    return x + (((size_t)(b * HIN + h) * WIN) + w) * (FIN * DIN);
}

// ---------------- pass 1: partial sum over c of preds (4 pos/warp) ----------
__global__ void __launch_bounds__(TPB, 2) k_pass1(const float* __restrict__ x) {
    extern __shared__ u64 sW[];   // 4 stages x 2048 u64 (64KB)
    int tid  = threadIdx.x;
    int lane = tid & 31;
    int w    = tid >> 5;
    int pos0 = blockIdx.x * POSB + w * 4;
    int cch  = blockIdx.y;
    int cbeg = cch * CPC;
    const int NT = CPC / 2;   // 18 duets

    const float* xb[4];
    #pragma unroll
    for (int q = 0; q < 4; ++q) xb[q] = pos_base(x, pos0 + q);

    u64 acc[4][8];
    #pragma unroll
    for (int q = 0; q < 4; ++q)
        #pragma unroll
        for (int p = 0; p < 8; ++p) acc[q][p] = 0ULL;

    // prologue: duets 0 and 1 (4 c's, one commit group each)
    #pragma unroll
    for (int j = 0; j < 4; ++j)
        stage_copy(sW + (size_t)j * 2048, g_Wq + (size_t)(cbeg + j) * 1024, tid);

    for (int t = 0; t < NT; ++t) {
        if (t + 1 < NT) wait_cp<2>(); else wait_cp<0>();
        __syncthreads();
        int sset = (t & 1) * 2;
        int dbeg = cbeg + t * 2;

        #pragma unroll
        for (int k = 0; k < 2; ++k) {
            int j = (w + k) & 1;          // rotated duet order per warp
            int c = dbeg + j;
            int off = c_koff[c >> 5] + (c & 31) * DIN;
            float xs[4][8];
            #pragma unroll
            for (int q = 0; q < 4; ++q) {
                float4 v0 = ((const float4*)(xb[q] + off))[0];
                float4 v1 = ((const float4*)(xb[q] + off))[1];
                xs[q][0]=v0.x; xs[q][1]=v0.y; xs[q][2]=v0.z; xs[q][3]=v0.w;
                xs[q][4]=v1.x; xs[q][5]=v1.y; xs[q][6]=v1.z; xs[q][7]=v1.w;
            }
            const ulonglong2* wb = (const ulonglong2*)(sW + (size_t)(sset + j) * 2048);
            #pragma unroll
            for (int i = 0; i < 8; ++i) {
                u64 xd0 = pk(xs[0][i], xs[0][i]);
                u64 xd1 = pk(xs[1][i], xs[1][i]);
                u64 xd2 = pk(xs[2][i], xs[2][i]);
                u64 xd3 = pk(xs[3][i], xs[3][i]);
                #pragma unroll
                for (int ph = 0; ph < 4; ++ph) {
                    ulonglong2 wv = wb[(i * 4 + ph) * 32 + lane];
                    acc[0][2*ph]   = fma2(wv.x, xd0, acc[0][2*ph]);
                    acc[1][2*ph]   = fma2(wv.x, xd1, acc[1][2*ph]);
                    acc[2][2*ph]   = fma2(wv.x, xd2, acc[2][2*ph]);
                    acc[3][2*ph]   = fma2(wv.x, xd3, acc[3][2*ph]);
                    acc[0][2*ph+1] = fma2(wv.y, xd0, acc[0][2*ph+1]);
                    acc[1][2*ph+1] = fma2(wv.y, xd1, acc[1][2*ph+1]);
                    acc[2][2*ph+1] = fma2(wv.y, xd2, acc[2][2*ph+1]);
                    acc[3][2*ph+1] = fma2(wv.y, xd3, acc[3][2*ph+1]);
                }
            }
        }

        __syncthreads();
        if (t + 2 < NT) {
            #pragma unroll
            for (int j = 0; j < 2; ++j)
                stage_copy(sW + (size_t)(sset + j) * 2048,
                           g_Wq + (size_t)(cbeg + (t + 2) * 2 + j) * 1024, tid);
        }
    }

    #pragma unroll
    for (int q = 0; q < 4; ++q) {
        u64* d = (u64*)g_S1p + (((size_t)cch * NPOS + pos0 + q) * FF + lane) * 8;
        #pragma unroll
        for (int p = 0; p < 8; ++p) d[p] = acc[q][p];
    }
}

// ---------------- squash 1: fp32 out1 pairs ----------------------------------
__global__ void k_squash1() {
    int t = blockIdx.x * blockDim.x + threadIdx.x;   // (pos,f)
    if (t >= NPOS * FF) return;
    float sx[8], sy[8];
    #pragma unroll
    for (int p = 0; p < 8; ++p) { sx[p] = 0.f; sy[p] = 0.f; }
    for (int ch = 0; ch < NCH; ++ch) {
        const float2* s = g_S1p + ((size_t)ch * NPOS * FF + t) * 8;
        #pragma unroll
        for (int p = 0; p < 8; ++p) { float2 v = s[p]; sx[p] += v.x; sy[p] += v.y; }
    }
    float sn = 0.f;
    #pragma unroll
    for (int p = 0; p < 8; ++p) {
        sx[p] *= (1.f / 32.f); sy[p] *= (1.f / 32.f);
        sn += sx[p] * sx[p] + sy[p] * sy[p];
    }
    float sc = (sn / (1.f + sn)) / sqrtf(sn + 1e-7f);
    float2* d = g_out1p + (size_t)t * 8;
    #pragma unroll
    for (int p = 0; p < 8; ++p) d[p] = make_float2(sx[p] * sc, sy[p] * sc);
}

// ---------------- pass 2: fused agreement/softmax(F)/centroid (4 pos/warp) --
__global__ void __launch_bounds__(TPB, 2) k_pass2(const float* __restrict__ x) {
    extern __shared__ u64 smem[];
    u64* sW  = smem;                       // 4 stages x 2048 u64 (64KB)
    u64* sO1 = smem + 4 * 2048;            // [p(8)][pos(16)][f(32)] u64 (32KB)

    int tid  = threadIdx.x;
    int lane = tid & 31;
    int w    = tid >> 5;
    int posb = blockIdx.x * POSB;
    int wpos = w * 4;
    int pos0 = posb + wpos;
    int cch  = blockIdx.y;
    int cbeg = cch * CPC;
    const int NT = CPC / 2;   // 18 duets

    const float* xb[4];
    #pragma unroll
    for (int q = 0; q < 4; ++q) xb[q] = pos_base(x, pos0 + q);

    // one-time: o1 (fp32 pairs) -> smem transposed to [p][pos][f]
    for (int idx = tid; idx < 8 * POSB * 32; idx += TPB) {
        int f    = idx & 31;
        int posl = (idx >> 5) & (POSB - 1);
        int p    = idx >> 9;
        sO1[(p * POSB + posl) * 32 + f] =
            ((const u64*)g_out1p)[(((size_t)(posb + posl) * FF) + f) * 8 + p];
    }

    u64 ce[4][8];
    #pragma unroll
    for (int q = 0; q < 4; ++q)
        #pragma unroll
        for (int p = 0; p < 8; ++p) ce[q][p] = 0ULL;

    #pragma unroll
    for (int j = 0; j < 4; ++j)
        stage_copy(sW + (size_t)j * 2048, g_Wq + (size_t)(cbeg + j) * 1024, tid);

    for (int t = 0; t < NT; ++t) {
        if (t + 1 < NT) wait_cp<2>(); else wait_cp<0>();
        __syncthreads();
        int sset = (t & 1) * 2;
        int dbeg = cbeg + t * 2;

        #pragma unroll
        for (int k = 0; k < 2; ++k) {
            int j = (w + k) & 1;          // rotated duet order per warp
            int c = dbeg + j;
            int off = c_koff[c >> 5] + (c & 31) * DIN;
            float xs[4][8];
            #pragma unroll
            for (int q = 0; q < 4; ++q) {
                float4 v0 = ((const float4*)(xb[q] + off))[0];
                float4 v1 = ((const float4*)(xb[q] + off))[1];
                xs[q][0]=v0.x; xs[q][1]=v0.y; xs[q][2]=v0.z; xs[q][3]=v0.w;
                xs[q][4]=v1.x; xs[q][5]=v1.y; xs[q][6]=v1.z; xs[q][7]=v1.w;
            }

            u64 pr[4][8];
            #pragma unroll
            for (int q = 0; q < 4; ++q)
                #pragma unroll
                for (int p = 0; p < 8; ++p) pr[q][p] = 0ULL;

            const ulonglong2* wb = (const ulonglong2*)(sW + (size_t)(sset + j) * 2048);
            #pragma unroll
            for (int i = 0; i < 8; ++i) {
                u64 xd0 = pk(xs[0][i], xs[0][i]);
                u64 xd1 = pk(xs[1][i], xs[1][i]);
                u64 xd2 = pk(xs[2][i], xs[2][i]);
                u64 xd3 = pk(xs[3][i], xs[3][i]);
                #pragma unroll
                for (int ph = 0; ph < 4; ++ph) {
                    ulonglong2 wv = wb[(i * 4 + ph) * 32 + lane];
                    pr[0][2*ph]   = fma2(wv.x, xd0, pr[0][2*ph]);
                    pr[1][2*ph]   = fma2(wv.x, xd1, pr[1][2*ph]);
                    pr[2][2*ph]   = fma2(wv.x, xd2, pr[2][2*ph]);
                    pr[3][2*ph]   = fma2(wv.x, xd3, pr[3][2*ph]);
                    pr[0][2*ph+1] = fma2(wv.y, xd0, pr[0][2*ph+1]);
                    pr[1][2*ph+1] = fma2(wv.y, xd1, pr[1][2*ph+1]);
                    pr[2][2*ph+1] = fma2(wv.y, xd2, pr[2][2*ph+1]);
                    pr[3][2*ph+1] = fma2(wv.y, xd3, pr[3][2*ph+1]);
                }
            }

            // agreement dots: o1 from smem (conflict-free LDS.64, lane=f)
            float e[4];
            #pragma unroll
            for (int q = 0; q < 4; ++q) {
                u64 a = 0ULL;
                #pragma unroll
                for (int p = 0; p < 8; ++p) {
                    u64 o1v = sO1[(p * POSB + wpos + q) * 32 + lane];
                    a = fma2(pr[q][p], o1v, a);
                }
                float l, h;
                upk(a, l, h);
                e[q] = __expf(l + h);   // no max-subtraction: |agreement| is O(1)
            }

            // 4 independent butterfly sums over f (lanes)
            float s0 = e[0], s1 = e[1], s2 = e[2], s3 = e[3];
            #pragma unroll
            for (int d = 16; d > 0; d >>= 1) {
                s0 += __shfl_xor_sync(0xffffffffu, s0, d);
                s1 += __shfl_xor_sync(0xffffffffu, s1, d);
                s2 += __shfl_xor_sync(0xffffffffu, s2, d);
                s3 += __shfl_xor_sync(0xffffffffu, s3, d);
            }
            float cc[4] = { __fdividef(e[0], s0), __fdividef(e[1], s1),
                            __fdividef(e[2], s2), __fdividef(e[3], s3) };

            #pragma unroll
            for (int q = 0; q < 4; ++q) {
                u64 cd = pk(cc[q], cc[q]);
                #pragma unroll
                for (int p = 0; p < 8; ++p)
                    ce[q][p] = fma2(pr[q][p], cd, ce[q][p]);
            }
        }

        __syncthreads();
        if (t + 2 < NT) {
            #pragma unroll
            for (int j = 0; j < 2; ++j)
                stage_copy(sW + (size_t)(sset + j) * 2048,
                           g_Wq + (size_t)(cbeg + (t + 2) * 2 + j) * 1024, tid);
        }
    }

    #pragma unroll
    for (int q = 0; q < 4; ++q) {
        u64* d = (u64*)g_centp + (((size_t)cch * NPOS + pos0 + q) * FF + lane) * 8;
        #pragma unroll
        for (int p = 0; p < 8; ++p) d[p] = ce[q][p];
    }
}

// ---------------- squash 2: final output ------------------------------------
__global__ void k_squash2(float* __restrict__ out) {
    int t = blockIdx.x * blockDim.x + threadIdx.x;   // (pos,f)
    if (t >= NPOS * FF) return;
    float sx[8], sy[8];
    #pragma unroll
    for (int p = 0; p < 8; ++p) { sx[p] = 0.f; sy[p] = 0.f; }
    for (int ch = 0; ch < NCH; ++ch) {
        const float2* s = g_centp + ((size_t)ch * NPOS * FF + t) * 8;
        #pragma unroll
        for (int p = 0; p < 8; ++p) { float2 v = s[p]; sx[p] += v.x; sy[p] += v.y; }
    }
    float sn = 0.f;
    #pragma unroll
    for (int p = 0; p < 8; ++p) sn += sx[p] * sx[p] + sy[p] * sy[p];
    float sc = (sn / (1.f + sn)) / sqrtf(sn + 1e-7f);
    float* d = out + (size_t)t * DOUT;
    #pragma unroll
    for (int p = 0; p < 8; ++p) { d[p] = sx[p] * sc; d[p + 8] = sy[p] * sc; }
}

// -----------------------------------------------------------------------------
extern "C" void kernel_launch(void* const* d_in, const int* in_sizes, int n_in,
                              void* d_out, int out_size) {
    const float* x = (const float*)d_in[0];
    const float* W = (const float*)d_in[1];
    if (n_in >= 2 && in_sizes[0] == (int)((size_t)FF * CCAP * DOUT * DIN)) {
        const float* t = x; x = W; W = t;
    }
    float* out = (float*)d_out;

    cudaFuncSetAttribute(k_pass1, cudaFuncAttributeMaxDynamicSharedMemorySize, SMEM1_BYTES);
    cudaFuncSetAttribute(k_pass2, cudaFuncAttributeMaxDynamicSharedMemorySize, SMEM2_BYTES);

    k_transpose<<<(CCAP * 8 * 4 * 32 + 255) / 256, 256>>>(W);
    k_pass1<<<dim3(NPB, NCH), TPB, SMEM1_BYTES>>>(x);
    k_squash1<<<(NPOS * FF + 255) / 256, 256>>>();
    k_pass2<<<dim3(NPB, NCH), TPB, SMEM2_BYTES>>>(x);
    k_squash2<<<(NPOS * FF + 255) / 256, 256>>>(out);
}

// round 11
// speedup vs baseline: 1.2590x; 1.2590x over previous
#include <cuda_runtime.h>
#include <math.h>
#include <stdint.h>

#define HIN     14
#define WIN     14
#define HO      12
#define WO      12
#define BATCH   4
#define FIN     32
#define DIN     8
#define FF      32
#define CCAP    288
#define DOUT    16
#define NPOS    (BATCH*HO*WO)   // 576
#define KDIM    (CCAP*DIN)      // 2304
#define NDIM    (FF*DOUT)       // 512

// ---------------- pass1 GEMM (tf32 mma) config -------------------------------
#define G_TM    64              // CTA M tile
#define G_TN    128             // CTA N tile
#define G_TK    32              // K stage
#define G_TPB   256             // 8 warps (2x4)
#define G_KSPL  4               // split-K chunks
#define G_KC    (KDIM/G_KSPL)   // 576 k per chunk
#define G_NSTG  (G_KC/G_TK)     // 18 stages
#define A_STR   36              // padded A row stride (floats)
#define B_STR   132             // padded B row stride (floats)
#define SMEM_A  (G_TM*A_STR)    // floats
#define SMEM_B  (G_TK*B_STR)
#define SMEM_G  ((SMEM_A + SMEM_B) * 2 * 4)   // bytes, double buffered

// ---------------- pass2 config (R7 best) -------------------------------------
#define TPB     256
#define POSB2   32
#define NPB2    (NPOS/POSB2)    // 18
#define NCH2    8
#define CPC2    (CCAP/NCH2)     // 36 (9 quartets)
#define SMEM_BYTES (8 * 2048 * 8)   // 8 stages x 16KB = 128KB

typedef unsigned long long u64;

// ---------------- scratch (static device globals) ---------------------------
__device__ float2 g_Wtp[(size_t)CCAP*8*8*32];          // pass2 W: [c][i][p][f] f32x2 pairs
__device__ float  g_Wb[(size_t)KDIM*NDIM];             // pass1 B: [k=(c,i)][n=(f,o)] tf32
__device__ float  g_C1[(size_t)G_KSPL*NPOS*NDIM];      // pass1 split-K partials
__device__ float2 g_out1p[(size_t)NPOS*FF*8];          // squash(iter1) fp32 pairs
__device__ float2 g_centp[(size_t)NCH2*NPOS*FF*8];     // pass2 partial centroids

__device__ __constant__ int c_koff[9] = {0, 256, 512, 3584, 3840, 4096, 7168, 7424, 7680};

// ---------------- helpers ----------------------------------------------------
__device__ __forceinline__ u64 pk(float lo, float hi) {
    u64 r; asm("mov.b64 %0,{%1,%2};" : "=l"(r) : "f"(lo), "f"(hi)); return r;
}
__device__ __forceinline__ void upk(u64 v, float& a, float& b) {
    asm("mov.b64 {%0,%1},%2;" : "=f"(a), "=f"(b) : "l"(v));
}
__device__ __forceinline__ u64 fma2(u64 a, u64 b, u64 c) {
    u64 d; asm("fma.rn.f32x2 %0,%1,%2,%3;" : "=l"(d) : "l"(a), "l"(b), "l"(c)); return d;
}
__device__ __forceinline__ uint32_t f2tf32(float v) {
    uint32_t r; asm("cvt.rna.tf32.f32 %0, %1;" : "=r"(r) : "f"(v)); return r;
}
__device__ __forceinline__ void mma_tf32(float c[4], const uint32_t a[4], const uint32_t b[2]) {
    asm volatile(
        "mma.sync.aligned.m16n8k8.row.col.f32.tf32.tf32.f32 "
        "{%0,%1,%2,%3}, {%4,%5,%6,%7}, {%8,%9}, {%0,%1,%2,%3};"
        : "+f"(c[0]), "+f"(c[1]), "+f"(c[2]), "+f"(c[3])
        : "r"(a[0]), "r"(a[1]), "r"(a[2]), "r"(a[3]), "r"(b[0]), "r"(b[1]));
}

__device__ __forceinline__ void cp16(uint32_t saddr, const void* gaddr) {
    asm volatile("cp.async.cg.shared.global [%0], [%1], 16;" :: "r"(saddr), "l"(gaddr));
}
template<int N>
__device__ __forceinline__ void wait_cp() {
    asm volatile("cp.async.wait_group %0;" :: "n"(N));
}
__device__ __forceinline__ void commit_cp() {
    asm volatile("cp.async.commit_group;");
}

__device__ __forceinline__ int pos_off(int pos) {   // float offset of pos in x
    int b = pos / (HO * WO);
    int r = pos % (HO * WO);
    int h = r / WO;
    int w = r % WO;
    return ((b * HIN + h) * WIN + w) * (FIN * DIN);
}

// ---------------- W transforms ------------------------------------------------
// pass2 layout: Wtp[c][i][p][f] pairs (W[f,c,p,i], W[f,c,p+8,i])
__global__ void k_transpose(const float* __restrict__ W) {
    int tid = blockIdx.x * blockDim.x + threadIdx.x;
    if (tid >= CCAP * 8 * 32) return;
    int f = tid & 31;
    int r = tid >> 5;
    int p = r & 7;
    int c = r >> 3;
    const float* row0 = W + (((size_t)f * CCAP + c) * DOUT + p) * DIN;
    const float* row8 = W + (((size_t)f * CCAP + c) * DOUT + p + 8) * DIN;
    float4 a0 = ((const float4*)row0)[0], a1 = ((const float4*)row0)[1];
    float4 b0 = ((const float4*)row8)[0], b1 = ((const float4*)row8)[1];
    float a[8] = {a0.x,a0.y,a0.z,a0.w,a1.x,a1.y,a1.z,a1.w};
    float b[8] = {b0.x,b0.y,b0.z,b0.w,b1.x,b1.y,b1.z,b1.w};
    #pragma unroll
    for (int i = 0; i < 8; ++i)
        g_Wtp[(((size_t)c * 8 + i) * 8 + p) * 32 + f] = make_float2(a[i], b[i]);
}

// pass1 layout: Wb[(c*8+i)][(f*16+o)] = tf32(W[f][c][o][i])
__global__ void k_transW(const float* __restrict__ W) {
    int tid = blockIdx.x * blockDim.x + threadIdx.x;   // (c,i,f)
    if (tid >= CCAP * 8 * 32) return;
    int f = tid & 31;
    int i = (tid >> 5) & 7;
    int c = tid >> 8;
    const float* src = W + (((size_t)f * CCAP + c) * DOUT) * DIN + i;
    float* dst = g_Wb + ((size_t)c * 8 + i) * NDIM + f * 16;
    #pragma unroll
    for (int o = 0; o < 16; ++o) {
        uint32_t t = f2tf32(src[o * DIN]);
        dst[o] = __uint_as_float(t);
    }
}

// ---------------- pass 1: tf32 MMA GEMM, split-K ------------------------------
// C1[chunk][pos][n] = sum over k-chunk of X[pos][k] * Wb[k][n]
__global__ void __launch_bounds__(G_TPB, 1) k_pass1mma(const float* __restrict__ x) {
    extern __shared__ float sm[];
    float* sA = sm;                                   // [2][64][A_STR]
    float* sB = sm + 2 * SMEM_A;                      // [2][32][B_STR]
    __shared__ int sPos[G_TM];

    int tid   = threadIdx.x;
    int lane  = tid & 31;
    int warp  = tid >> 5;
    int wm    = warp >> 2;          // 0..1
    int wn    = warp & 3;           // 0..3
    int mtile = blockIdx.x;         // 9
    int ntile = blockIdx.y;         // 4
    int chunk = blockIdx.z;         // 4
    int cq0   = chunk * (G_KC / 8); // first c of chunk (72 c's per chunk)

    if (tid < G_TM) sPos[tid] = pos_off(mtile * G_TM + tid);
    __syncthreads();

    float acc[2][4][4];
    #pragma unroll
    for (int mt = 0; mt < 2; ++mt)
        #pragma unroll
        for (int nt = 0; nt < 4; ++nt)
            #pragma unroll
            for (int q = 0; q < 4; ++q) acc[mt][nt][q] = 0.f;

    // stage loader: A 512 chunks (2/thread), B 1024 chunks (4/thread)
    auto load_stage = [&](int s, int buf) {
        int cq  = cq0 + s * 4;                        // 4 c's per stage, kk-aligned
        int aoff = c_koff[cq >> 5] + (cq & 31) * DIN; // float offset in x row
        float* dA = sA + buf * SMEM_A;
        uint32_t sa = (uint32_t)__cvta_generic_to_shared(dA);
        #pragma unroll
        for (int j = 0; j < 2; ++j) {
            int idx = tid + j * G_TPB;                // 0..511
            int row = idx >> 3;
            int c16 = idx & 7;
            cp16(sa + (row * A_STR + c16 * 4) * 4,
                 x + sPos[row] + aoff + c16 * 4);
        }
        const float* gB = g_Wb + ((size_t)chunk * G_KC + s * G_TK) * NDIM + ntile * G_TN;
        float* dB = sB + buf * SMEM_B;
        uint32_t sb = (uint32_t)__cvta_generic_to_shared(dB);
        #pragma unroll
        for (int j = 0; j < 4; ++j) {
            int idx = tid + j * G_TPB;                // 0..1023
            int k   = idx >> 5;
            int c16 = idx & 31;
            cp16(sb + (k * B_STR + c16 * 4) * 4,
                 gB + (size_t)k * NDIM + c16 * 4);
        }
        commit_cp();
    };

    load_stage(0, 0);
    load_stage(1, 1);

    for (int s = 0; s < G_NSTG; ++s) {
        if (s + 1 < G_NSTG) wait_cp<1>(); else wait_cp<0>();
        __syncthreads();
        int buf = s & 1;
        const float* A = sA + buf * SMEM_A;
        const float* B = sB + buf * SMEM_B;

        #pragma unroll
        for (int k8 = 0; k8 < 4; ++k8) {
            int k0 = k8 * 8;
            uint32_t af[2][4];
            #pragma unroll
            for (int mt = 0; mt < 2; ++mt) {
                int row = wm * 32 + mt * 16 + (lane >> 2);
                int kk  = k0 + (lane & 3);
                af[mt][0] = f2tf32(A[row * A_STR + kk]);
                af[mt][1] = f2tf32(A[(row + 8) * A_STR + kk]);
                af[mt][2] = f2tf32(A[row * A_STR + kk + 4]);
                af[mt][3] = f2tf32(A[(row + 8) * A_STR + kk + 4]);
            }
            uint32_t bf[4][2];
            #pragma unroll
            for (int nt = 0; nt < 4; ++nt) {
                int col = wn * 32 + nt * 8 + (lane >> 2);
                int kk  = k0 + (lane & 3);
                bf[nt][0] = __float_as_uint(B[kk * B_STR + col]);
                bf[nt][1] = __float_as_uint(B[(kk + 4) * B_STR + col]);
            }
            #pragma unroll
            for (int mt = 0; mt < 2; ++mt)
                #pragma unroll
                for (int nt = 0; nt < 4; ++nt)
                    mma_tf32(acc[mt][nt], af[mt], bf[nt]);
        }

        __syncthreads();
        if (s + 2 < G_NSTG) load_stage(s + 2, buf);
    }

    // epilogue: write fp32 partials
    #pragma unroll
    for (int mt = 0; mt < 2; ++mt) {
        int row = mtile * G_TM + wm * 32 + mt * 16 + (lane >> 2);
        #pragma unroll
        for (int nt = 0; nt < 4; ++nt) {
            int col = ntile * G_TN + wn * 32 + nt * 8 + (lane & 3) * 2;
            float* d0 = g_C1 + ((size_t)chunk * NPOS + row) * NDIM + col;
            float* d1 = g_C1 + ((size_t)chunk * NPOS + row + 8) * NDIM + col;
            d0[0] = acc[mt][nt][0]; d0[1] = acc[mt][nt][1];
            d1[0] = acc[mt][nt][2]; d1[1] = acc[mt][nt][3];
        }
    }
}

// ---------------- squash 1: reduce split-K, squash, pack pairs ---------------
__global__ void k_squash1() {
    int t = blockIdx.x * blockDim.x + threadIdx.x;   // (pos,f)
    if (t >= NPOS * FF) return;
    int pos = t >> 5;
    int f   = t & 31;
    float s[16];
    #pragma unroll
    for (int o = 0; o < 16; ++o) s[o] = 0.f;
    #pragma unroll
    for (int ch = 0; ch < G_KSPL; ++ch) {
        const float4* p = (const float4*)(g_C1 + ((size_t)ch * NPOS + pos) * NDIM + f * 16);
        #pragma unroll
        for (int q = 0; q < 4; ++q) {
            float4 v = p[q];
            s[q*4] += v.x; s[q*4+1] += v.y; s[q*4+2] += v.z; s[q*4+3] += v.w;
        }
    }
    float sn = 0.f;
    #pragma unroll
    for (int o = 0; o < 16; ++o) { s[o] *= (1.f / 32.f); sn += s[o] * s[o]; }
    float sc = (sn / (1.f + sn)) / sqrtf(sn + 1e-7f);
    float2* d = g_out1p + (size_t)t * 8;
    #pragma unroll
    for (int p = 0; p < 8; ++p) d[p] = make_float2(s[p] * sc, s[p + 8] * sc);
}

// ---------------- pass2 smem stage copy (16KB W tile) -------------------------
__device__ __forceinline__ void stage_copy(u64* sdst, const float2* gsrc, int tid) {
    uint32_t s = (uint32_t)__cvta_generic_to_shared(sdst);
    const char* g = (const char*)gsrc;
    #pragma unroll
    for (int k = 0; k < 4; ++k) {
        int idx = tid + k * TPB;
        cp16(s + idx * 16, g + (size_t)idx * 16);
    }
    commit_cp();
}

__device__ __forceinline__ const float* pos_base(const float* x, int pos) {
    return x + pos_off(pos);
}

// ---------------- pass 2: fused agreement/softmax(F)/centroid (R7 config) ----
__global__ void __launch_bounds__(TPB, 1) k_pass2(const float* __restrict__ x) {
    extern __shared__ u64 sW[];   // 8 stages x 2048 u64
    int tid  = threadIdx.x;
    int lane = tid & 31;
    int w    = tid >> 5;
    int pos0 = blockIdx.x * POSB2 + w * 4;
    int cch  = blockIdx.y;
    int cbeg = cch * CPC2;
    const int NT = CPC2 / 4;   // 9 quartets

    const float* xb[4];
    #pragma unroll
    for (int q = 0; q < 4; ++q) xb[q] = pos_base(x, pos0 + q);

    u64 o1[4][8];
    #pragma unroll
    for (int q = 0; q < 4; ++q) {
        const u64* s = (const u64*)g_out1p + (((size_t)(pos0 + q) * FF) + lane) * 8;
        #pragma unroll
        for (int p = 0; p < 8; ++p) o1[q][p] = s[p];
    }

    u64 ce[4][8];
    #pragma unroll
    for (int q = 0; q < 4; ++q)
        #pragma unroll
        for (int p = 0; p < 8; ++p) ce[q][p] = 0ULL;

    #pragma unroll
    for (int j = 0; j < 4; ++j)
        stage_copy(sW + (size_t)j * 2048, g_Wtp + (size_t)(cbeg + j) * 2048, tid);
    #pragma unroll
    for (int j = 0; j < 4; ++j)
        stage_copy(sW + (size_t)(4 + j) * 2048, g_Wtp + (size_t)(cbeg + 4 + j) * 2048, tid);

    for (int t = 0; t < NT; ++t) {
        if (t + 1 < NT) wait_cp<4>(); else wait_cp<0>();
        __syncthreads();
        int sset = (t & 1) * 4;
        int qbeg = cbeg + t * 4;

        #pragma unroll
        for (int k = 0; k < 4; ++k) {
            int j = (w + k) & 3;
            int c = qbeg + j;
            int off = c_koff[c >> 5] + (c & 31) * DIN;
            float xs[4][8];
            #pragma unroll
            for (int q = 0; q < 4; ++q) {
                float4 v0 = ((const float4*)(xb[q] + off))[0];
                float4 v1 = ((const float4*)(xb[q] + off))[1];
                xs[q][0]=v0.x; xs[q][1]=v0.y; xs[q][2]=v0.z; xs[q][3]=v0.w;
                xs[q][4]=v1.x; xs[q][5]=v1.y; xs[q][6]=v1.z; xs[q][7]=v1.w;
            }

            u64 pr[4][8];
            #pragma unroll
            for (int q = 0; q < 4; ++q)
                #pragma unroll
                for (int p = 0; p < 8; ++p) pr[q][p] = 0ULL;

            const u64* wb = sW + (size_t)(sset + j) * 2048;
            #pragma unroll
            for (int i = 0; i < 8; ++i) {
                u64 xd0 = pk(xs[0][i], xs[0][i]);
                u64 xd1 = pk(xs[1][i], xs[1][i]);
                u64 xd2 = pk(xs[2][i], xs[2][i]);
                u64 xd3 = pk(xs[3][i], xs[3][i]);
                #pragma unroll
                for (int p = 0; p < 8; ++p) {
                    u64 wv = wb[(i * 8 + p) * 32 + lane];
                    pr[0][p] = fma2(wv, xd0, pr[0][p]);
                    pr[1][p] = fma2(wv, xd1, pr[1][p]);
                    pr[2][p] = fma2(wv, xd2, pr[2][p]);
                    pr[3][p] = fma2(wv, xd3, pr[3][p]);
                }
            }

            float e[4];
            #pragma unroll
            for (int q = 0; q < 4; ++q) {
                u64 a = 0ULL;
                #pragma unroll
                for (int p = 0; p < 8; ++p) a = fma2(pr[q][p], o1[q][p], a);
                float l, h;
                upk(a, l, h);
                e[q] = __expf(l + h);   // no max-subtraction: |agreement| is O(1)
            }

            float s0 = e[0], s1 = e[1], s2 = e[2], s3 = e[3];
            #pragma unroll
            for (int d = 16; d > 0; d >>= 1) {
                s0 += __shfl_xor_sync(0xffffffffu, s0, d);
                s1 += __shfl_xor_sync(0xffffffffu, s1, d);
                s2 += __shfl_xor_sync(0xffffffffu, s2, d);
                s3 += __shfl_xor_sync(0xffffffffu, s3, d);
            }
            float cc[4] = { __fdividef(e[0], s0), __fdividef(e[1], s1),
                            __fdividef(e[2], s2), __fdividef(e[3], s3) };

            #pragma unroll
            for (int q = 0; q < 4; ++q) {
                u64 cd = pk(cc[q], cc[q]);
                #pragma unroll
                for (int p = 0; p < 8; ++p)
                    ce[q][p] = fma2(pr[q][p], cd, ce[q][p]);
            }
        }

        __syncthreads();
        if (t + 2 < NT) {
            #pragma unroll
            for (int j = 0; j < 4; ++j)
                stage_copy(sW + (size_t)(sset + j) * 2048,
                           g_Wtp + (size_t)(cbeg + (t + 2) * 4 + j) * 2048, tid);
        }
    }

    #pragma unroll
    for (int q = 0; q < 4; ++q) {
        u64* d = (u64*)g_centp + (((size_t)cch * NPOS + pos0 + q) * FF + lane) * 8;
        #pragma unroll
        for (int p = 0; p < 8; ++p) d[p] = ce[q][p];
    }
}

// ---------------- squash 2: final output ------------------------------------
__global__ void k_squash2(float* __restrict__ out) {
    int t = blockIdx.x * blockDim.x + threadIdx.x;   // (pos,f)
    if (t >= NPOS * FF) return;
    float sx[8], sy[8];
    #pragma unroll
    for (int p = 0; p < 8; ++p) { sx[p] = 0.f; sy[p] = 0.f; }
    for (int ch = 0; ch < NCH2; ++ch) {
        const float2* s = g_centp + ((size_t)ch * NPOS * FF + t) * 8;
        #pragma unroll
        for (int p = 0; p < 8; ++p) { float2 v = s[p]; sx[p] += v.x; sy[p] += v.y; }
    }
    float sn = 0.f;
    #pragma unroll
    for (int p = 0; p < 8; ++p) sn += sx[p] * sx[p] + sy[p] * sy[p];
    float sc = (sn / (1.f + sn)) / sqrtf(sn + 1e-7f);
    float* d = out + (size_t)t * DOUT;
    #pragma unroll
    for (int p = 0; p < 8; ++p) { d[p] = sx[p] * sc; d[p + 8] = sy[p] * sc; }
}

// -----------------------------------------------------------------------------
extern "C" void kernel_launch(void* const* d_in, const int* in_sizes, int n_in,
                              void* d_out, int out_size) {
    const float* x = (const float*)d_in[0];
    const float* W = (const float*)d_in[1];
    if (n_in >= 2 && in_sizes[0] == (int)((size_t)FF * CCAP * DOUT * DIN)) {
        const float* t = x; x = W; W = t;
    }
    float* out = (float*)d_out;

    cudaFuncSetAttribute(k_pass1mma, cudaFuncAttributeMaxDynamicSharedMemorySize, SMEM_G);
    cudaFuncSetAttribute(k_pass2, cudaFuncAttributeMaxDynamicSharedMemorySize, SMEM_BYTES);

    k_transpose<<<(CCAP * 8 * 32 + 255) / 256, 256>>>(W);
    k_transW<<<(CCAP * 8 * 32 + 255) / 256, 256>>>(W);
    k_pass1mma<<<dim3(NPOS / G_TM, NDIM / G_TN, G_KSPL), G_TPB, SMEM_G>>>(x);
    k_squash1<<<(NPOS * FF + 255) / 256, 256>>>();
    k_pass2<<<dim3(NPB2, NCH2), TPB, SMEM_BYTES>>>(x);
    k_squash2<<<(NPOS * FF + 255) / 256, 256>>>(out);
}